// round 3
// baseline (speedup 1.0000x reference)
#include <cuda_runtime.h>

// Problem constants (fixed shapes for this problem instance)
constexpr int N_   = 2048;   // nodes
constexpr int F_   = 512;    // features
constexpr int M_   = 10;     // chebyshev order
constexpr int Q_   = 64;     // quadrature points
constexpr int ELL  = 64;     // max nnz per row of L_hat (expected ~16, 12-sigma safe)
constexpr float THRESH = 1e-5f;

// Scratch: __device__ globals (sanctioned; no cudaMalloc allowed)
__device__ float g_T[3][N_ * N_];       // ping-pong Chebyshev T_k buffers (3 x 16.8 MB)
__device__ float g_H[N_ * N_];          // accumulated heat kernel
__device__ float g_c[N_ * (M_ + 1)];    // per-node Chebyshev coefficients
__device__ float g_Lval[N_ * ELL];      // ELL sparse L_hat values
__device__ int   g_Lcol[N_ * ELL];      // ELL sparse L_hat column indices
__device__ int   g_Lcnt[N_];            // nnz per row

// ---------------------------------------------------------------------------
// Kernel 1: per-node Chebyshev-Gauss quadrature coefficients c[i, 0..M]
// ---------------------------------------------------------------------------
__global__ void k_coeff(const float* __restrict__ t, const float* __restrict__ eigmax) {
    int i = blockIdx.x * blockDim.x + threadIdx.x;
    if (i >= N_) return;
    float s  = expf(t[i]);
    float em = eigmax[0];
    float acc[M_ + 1];
#pragma unroll
    for (int k = 0; k <= M_; k++) acc[k] = 0.0f;

    const float PI = 3.14159265358979323846f;
    for (int q = 0; q < Q_; q++) {
        float theta = PI * ((float)q + 0.5f) / (float)Q_;
        float ct    = cosf(theta);
        float lam   = em * 0.5f * (ct + 1.0f);
        float w     = expf(-s * lam);
        // cos(k*theta) via Chebyshev recurrence
        float ckm1 = 1.0f;   // cos(0)
        float ck   = ct;     // cos(theta)
        acc[0] += w;
        acc[1] += w * ck;
#pragma unroll
        for (int k = 2; k <= M_; k++) {
            float cn = 2.0f * ct * ck - ckm1;
            ckm1 = ck; ck = cn;
            acc[k] += w * cn;
        }
    }
    float scale = 2.0f / (float)Q_;
#pragma unroll
    for (int k = 0; k <= M_; k++) {
        float v = scale * acc[k];
        if (k == 0) v *= 0.5f;
        g_c[i * (M_ + 1) + k] = v;
    }
}

// ---------------------------------------------------------------------------
// Kernel 2: extract sparse (ELL) structure of L_hat = (2/eigmax)*P_n - I.
// One warp per row; deterministic ballot-based ordered compaction.
// ---------------------------------------------------------------------------
__global__ void k_build(const float* __restrict__ P, const float* __restrict__ eigmax) {
    int warps_per_blk = blockDim.x >> 5;
    int row  = blockIdx.x * warps_per_blk + (threadIdx.x >> 5);
    int lane = threadIdx.x & 31;
    if (row >= N_) return;
    float sc = 2.0f / eigmax[0];
    int cnt = 0;
    for (int base = 0; base < N_; base += 32) {
        int col = base + lane;
        float v = sc * P[(size_t)row * N_ + col] - (col == row ? 1.0f : 0.0f);
        unsigned m = __ballot_sync(0xffffffffu, v != 0.0f);
        if (v != 0.0f) {
            int pos = cnt + __popc(m & ((1u << lane) - 1u));
            if (pos < ELL) {
                g_Lval[row * ELL + pos] = v;
                g_Lcol[row * ELL + pos] = col;
            }
        }
        cnt += __popc(m);
    }
    if (lane == 0) g_Lcnt[row] = cnt < ELL ? cnt : ELL;
}

// ---------------------------------------------------------------------------
// Kernel 3: init T0 = I, T1 = L_hat (dense), H = c0*I + c1*L_hat (vectorized)
// ---------------------------------------------------------------------------
__global__ void k_init(const float* __restrict__ P, const float* __restrict__ eigmax) {
    int idx = blockIdx.x * blockDim.x + threadIdx.x;   // over N*N/4 float4s
    if (idx >= N_ * N_ / 4) return;
    int i    = idx >> 9;          // / (N_/4) = 512
    int c4   = idx & 511;
    int col0 = c4 * 4;
    float sc = 2.0f / eigmax[0];

    float4 p = reinterpret_cast<const float4*>(P)[idx];
    float4 l = make_float4(sc * p.x, sc * p.y, sc * p.z, sc * p.w);
    float4 t0 = make_float4(0.f, 0.f, 0.f, 0.f);
    int d = i - col0;
    if (d >= 0 && d < 4) {
        reinterpret_cast<float*>(&l)[d]  -= 1.0f;
        reinterpret_cast<float*>(&t0)[d]  = 1.0f;
    }
    reinterpret_cast<float4*>(g_T[1])[idx] = l;
    reinterpret_cast<float4*>(g_T[0])[idx] = t0;

    float c0 = g_c[i * (M_ + 1) + 0];
    float c1 = g_c[i * (M_ + 1) + 1];
    float4 h = make_float4(c0 * t0.x + c1 * l.x,
                           c0 * t0.y + c1 * l.y,
                           c0 * t0.z + c1 * l.z,
                           c0 * t0.w + c1 * l.w);
    reinterpret_cast<float4*>(g_H)[idx] = h;
}

// ---------------------------------------------------------------------------
// Kernel 4: one Chebyshev recurrence step (fused SpMM + H accumulate).
// T_new = 2 * L_sparse @ T_cur - T_prev ;  H += c[:,k] * T_new
// One block per row, 512 threads, each handles one float4 column group.
// ---------------------------------------------------------------------------
__global__ void __launch_bounds__(512) k_step(int ip, int ic, int inew, int k) {
    const float* __restrict__ Tprev = g_T[ip];
    const float* __restrict__ Tcur  = g_T[ic];
    float*       __restrict__ Tnew  = g_T[inew];

    int row = blockIdx.x;
    __shared__ float sval[ELL];
    __shared__ int   scol[ELL];
    int cnt = g_Lcnt[row];
    if (threadIdx.x < ELL) {
        sval[threadIdx.x] = g_Lval[row * ELL + threadIdx.x];
        scol[threadIdx.x] = g_Lcol[row * ELL + threadIdx.x];
    }
    __syncthreads();

    float ck = g_c[row * (M_ + 1) + k];
    int c4 = threadIdx.x;   // 0..511 (N_/4 column groups)
    const float4* Tc4 = reinterpret_cast<const float4*>(Tcur);

    float4 acc = make_float4(0.f, 0.f, 0.f, 0.f);
#pragma unroll 4
    for (int tnz = 0; tnz < cnt; tnz++) {
        float v = sval[tnz];
        int   j = scol[tnz];
        float4 b = __ldg(&Tc4[j * (N_ / 4) + c4]);
        acc.x = fmaf(v, b.x, acc.x);
        acc.y = fmaf(v, b.y, acc.y);
        acc.z = fmaf(v, b.z, acc.z);
        acc.w = fmaf(v, b.w, acc.w);
    }
    int o = row * (N_ / 4) + c4;
    float4 p = reinterpret_cast<const float4*>(Tprev)[o];
    float4 tn = make_float4(2.0f * acc.x - p.x, 2.0f * acc.y - p.y,
                            2.0f * acc.z - p.z, 2.0f * acc.w - p.w);
    reinterpret_cast<float4*>(Tnew)[o] = tn;

    float4* H4 = reinterpret_cast<float4*>(g_H);
    float4 h = H4[o];
    h.x = fmaf(ck, tn.x, h.x);
    h.y = fmaf(ck, tn.y, h.y);
    h.z = fmaf(ck, tn.z, h.z);
    h.w = fmaf(ck, tn.w, h.w);
    H4[o] = h;
}

// ---------------------------------------------------------------------------
// Kernel 5: out = threshold(H) @ x.  Tiled fp32 SGEMM, 64x64x16 tiles,
// 256 threads, 4x4 microtile. Threshold applied when loading the H tile.
// ---------------------------------------------------------------------------
constexpr int BM = 64, BN = 64, BK = 16;

__global__ void __launch_bounds__(256) k_gemm(const float* __restrict__ X,
                                              float* __restrict__ out) {
    __shared__ float As[BK][BM + 4];   // As[k][i], padded
    __shared__ float Bs[BK][BN];       // Bs[k][f]

    int f0 = blockIdx.x * BN;
    int i0 = blockIdx.y * BM;
    int tid = threadIdx.x;
    int tx = tid & 15;        // 0..15 -> 4 output cols each
    int ty = tid >> 4;        // 0..15 -> 4 output rows each

    float acc[4][4];
#pragma unroll
    for (int r = 0; r < 4; r++)
#pragma unroll
        for (int s = 0; s < 4; s++) acc[r][s] = 0.0f;

    // A-load mapping: thread -> row i0 + tid/4, k-quad (tid%4)*4
    int a_i  = tid >> 2;
    int a_k0 = (tid & 3) * 4;
    // B-load mapping: thread -> k = tid/16, f-quad (tid%16)*4
    int b_k  = tid >> 4;
    int b_f0 = (tid & 15) * 4;

    for (int kt = 0; kt < N_; kt += BK) {
        // load + threshold A tile (64 x 16), store transposed
        float4 a = reinterpret_cast<const float4*>(
                       &g_H[(size_t)(i0 + a_i) * N_ + kt + a_k0])[0];
        a.x = (a.x < THRESH) ? 0.0f : a.x;
        a.y = (a.y < THRESH) ? 0.0f : a.y;
        a.z = (a.z < THRESH) ? 0.0f : a.z;
        a.w = (a.w < THRESH) ? 0.0f : a.w;
        As[a_k0 + 0][a_i] = a.x;
        As[a_k0 + 1][a_i] = a.y;
        As[a_k0 + 2][a_i] = a.z;
        As[a_k0 + 3][a_i] = a.w;
        // load B tile (16 x 64)
        float4 b = reinterpret_cast<const float4*>(
                       &X[(size_t)(kt + b_k) * F_ + f0 + b_f0])[0];
        *reinterpret_cast<float4*>(&Bs[b_k][b_f0]) = b;
        __syncthreads();

#pragma unroll
        for (int kk = 0; kk < BK; kk++) {
            float4 av = *reinterpret_cast<const float4*>(&As[kk][ty * 4]);
            float4 bv = *reinterpret_cast<const float4*>(&Bs[kk][tx * 4]);
            const float* ap = reinterpret_cast<const float*>(&av);
            const float* bp = reinterpret_cast<const float*>(&bv);
#pragma unroll
            for (int r = 0; r < 4; r++)
#pragma unroll
                for (int s = 0; s < 4; s++)
                    acc[r][s] = fmaf(ap[r], bp[s], acc[r][s]);
        }
        __syncthreads();
    }

#pragma unroll
    for (int r = 0; r < 4; r++) {
        float4 v = make_float4(acc[r][0], acc[r][1], acc[r][2], acc[r][3]);
        reinterpret_cast<float4*>(
            &out[(size_t)(i0 + ty * 4 + r) * F_ + f0 + tx * 4])[0] = v;
    }
}

// ---------------------------------------------------------------------------
// Kernel 6: second reference output is t itself -> copy to tail of d_out
// ---------------------------------------------------------------------------
__global__ void k_copy_t(const float* __restrict__ t, float* __restrict__ out) {
    int i = blockIdx.x * blockDim.x + threadIdx.x;
    if (i < N_) out[(size_t)N_ * F_ + i] = t[i];
}

// ---------------------------------------------------------------------------
extern "C" void kernel_launch(void* const* d_in, const int* in_sizes, int n_in,
                              void* d_out, int out_size) {
    const float* x   = (const float*)d_in[0];   // [N, F]
    const float* P   = (const float*)d_in[1];   // [N, N]
    const float* t   = (const float*)d_in[2];   // [N]
    const float* eig = (const float*)d_in[3];   // [1]
    float* out = (float*)d_out;

    k_coeff<<<(N_ + 255) / 256, 256>>>(t, eig);
    k_build<<<N_ / 8, 256>>>(P, eig);            // 8 warps/block, 1 warp/row
    k_init<<<(N_ * N_ / 4 + 255) / 256, 256>>>(P, eig);

    int ip = 0, ic = 1, inew = 2;
    for (int k = 2; k <= M_; k++) {
        k_step<<<N_, 512>>>(ip, ic, inew, k);
        int tmp = ip; ip = ic; ic = inew; inew = tmp;
    }

    dim3 gg(F_ / BN, N_ / BM);
    k_gemm<<<gg, 256>>>(x, out);

    if (out_size >= N_ * F_ + N_)
        k_copy_t<<<(N_ + 255) / 256, 256>>>(t, out);
}